// round 7
// baseline (speedup 1.0000x reference)
#include <cuda_runtime.h>
#include <cstdint>

#define BATCH   8192
#define LMAX    100
#define DIM     128
#define DIM2    256

// Scratch (device globals: no allocation allowed)
__device__ float g_H [BATCH * DIM2];
__device__ float g_T1[BATCH * DIM2];
__device__ float g_T2[BATCH * DIM2];

#define FMA2(acc, a, b) \
    asm("fma.rn.f32x2 %0, %1, %2, %0;" : "+l"(acc) : "l"(a), "l"(b))
#define PACKDUP(out, f) \
    asm("mov.b64 %0, {%1, %1};" : "=l"(out) : "r"(__float_as_uint(f)))

// ---------------------------------------------------------------------------
// Kernel 1: fused single-pass attention + concat. One CTA (128 thr) / bundle.
// Softmax without max-subtraction (scores are O(1); ratio identical).
// Per warp-iteration: EIGHT items in two 4-item slots (8 lanes/item);
// all 16 LDG.128 per lane issued up front, then two independent 3-shfl
// reductions -> exp -> accumulate.  Scratch H written with evict-first (.cs)
// so the 102 MB embedding tables keep L2.
// ---------------------------------------------------------------------------
__global__ __launch_bounds__(128) void attn_kernel(
    const int*  __restrict__ x_u,
    const int*  __restrict__ x_b,
    const int*  __restrict__ items,
    const int*  __restrict__ mask,     // int32 prefix flags
    const float* __restrict__ emb_u,
    const float* __restrict__ emb_i,
    const float* __restrict__ emb_b,
    const float* __restrict__ A)
{
    const int b    = blockIdx.x;
    const int tid  = threadIdx.x;
    const int warp = tid >> 5;
    const int lane = tid & 31;
    const int g    = lane >> 3;          // item slot within group (0..3)
    const int lg   = lane & 7;           // lane within 8-lane item group

    __shared__ float s_hu[DIM];
    __shared__ float s_acc[4][DIM];
    __shared__ float s_sw[4];
    __shared__ int   s_it[LMAX];
    __shared__ int   s_cnt[4];

    const int xu = x_u[b];
    const int xb = x_b[b];

    s_hu[tid] = emb_u[(size_t)xu * DIM + tid];
    const float hb = emb_b[(size_t)xb * DIM + tid];   // prefetch

    const int* it_row = items + (size_t)b * LMAX;
    const int* mk_row = mask  + (size_t)b * LMAX;
    int v = 0;
    if (tid < LMAX) {
        v = (__ldcs(mk_row + tid) != 0) ? 1 : 0;
        s_it[tid] = __ldcs(it_row + tid);
    }
    #pragma unroll
    for (int o = 16; o > 0; o >>= 1)
        v += __shfl_xor_sync(0xffffffffu, v, o);
    if (lane == 0) s_cnt[warp] = v;
    __syncthreads();
    const int n = s_cnt[0] + s_cnt[1] + s_cnt[2] + s_cnt[3];   // >= 10

    float4 hu[4];
    #pragma unroll
    for (int j = 0; j < 4; j++)
        hu[j] = *(const float4*)(s_hu + (j * 8 + lg) * 4);

    float4 acc[4];
    #pragma unroll
    for (int j = 0; j < 4; j++) acc[j] = make_float4(0.f, 0.f, 0.f, 0.f);
    float s = 0.f;

    // warp w covers items [w*8 .. w*8+7], stepping 32
    for (int base = warp * 8; base < n; base += 32) {
        const int  la = base + g;
        const int  lb = base + 4 + g;
        const bool va = (la < n);
        const bool vb = (lb < n);
        const int  ia = s_it[va ? la : (n - 1)];
        const int  ib = s_it[vb ? lb : (n - 1)];

        const float4* arA = (const float4*)(A     + (size_t)ia * DIM);
        const float4* erA = (const float4*)(emb_i + (size_t)ia * DIM);
        const float4* arB = (const float4*)(A     + (size_t)ib * DIM);
        const float4* erB = (const float4*)(emb_i + (size_t)ib * DIM);

        float4 aA[4], eA[4], aB[4], eB[4];
        #pragma unroll
        for (int j = 0; j < 4; j++) aA[j] = arA[j * 8 + lg];
        #pragma unroll
        for (int j = 0; j < 4; j++) aB[j] = arB[j * 8 + lg];
        #pragma unroll
        for (int j = 0; j < 4; j++) eA[j] = erA[j * 8 + lg];
        #pragma unroll
        for (int j = 0; j < 4; j++) eB[j] = erB[j * 8 + lg];

        float pa = 0.f, pb = 0.f;
        #pragma unroll
        for (int j = 0; j < 4; j++) {
            pa += hu[j].x * aA[j].x + hu[j].y * aA[j].y
                + hu[j].z * aA[j].z + hu[j].w * aA[j].w;
            pb += hu[j].x * aB[j].x + hu[j].y * aB[j].y
                + hu[j].z * aB[j].z + hu[j].w * aB[j].w;
        }
        pa += __shfl_xor_sync(0xffffffffu, pa, 4);
        pb += __shfl_xor_sync(0xffffffffu, pb, 4);
        pa += __shfl_xor_sync(0xffffffffu, pa, 2);
        pb += __shfl_xor_sync(0xffffffffu, pb, 2);
        pa += __shfl_xor_sync(0xffffffffu, pa, 1);
        pb += __shfl_xor_sync(0xffffffffu, pb, 1);

        const float ea = va ? __expf(pa) : 0.f;
        const float eb = vb ? __expf(pb) : 0.f;
        s += ea + eb;
        #pragma unroll
        for (int j = 0; j < 4; j++) {
            acc[j].x += ea * eA[j].x + eb * eB[j].x;
            acc[j].y += ea * eA[j].y + eb * eB[j].y;
            acc[j].z += ea * eA[j].z + eb * eB[j].z;
            acc[j].w += ea * eA[j].w + eb * eB[j].w;
        }
    }

    // combine the 4 item-groups of this warp (xor 8, then 16)
    #pragma unroll
    for (int o = 8; o <= 16; o <<= 1) {
        s += __shfl_xor_sync(0xffffffffu, s, o);
        #pragma unroll
        for (int j = 0; j < 4; j++) {
            acc[j].x += __shfl_xor_sync(0xffffffffu, acc[j].x, o);
            acc[j].y += __shfl_xor_sync(0xffffffffu, acc[j].y, o);
            acc[j].z += __shfl_xor_sync(0xffffffffu, acc[j].z, o);
            acc[j].w += __shfl_xor_sync(0xffffffffu, acc[j].w, o);
        }
    }
    if (g == 0) {
        #pragma unroll
        for (int j = 0; j < 4; j++)
            *(float4*)(&s_acc[warp][(j * 8 + lg) * 4]) = acc[j];
        if (lg == 0) s_sw[warp] = s;
    }
    __syncthreads();

    const float hx  = s_acc[0][tid] + s_acc[1][tid] + s_acc[2][tid] + s_acc[3][tid];
    const float tot = s_sw[0] + s_sw[1] + s_sw[2] + s_sw[3];
    float* Hrow = g_H + (size_t)b * DIM2;
    __stcs(Hrow + tid,       s_hu[tid]);
    __stcs(Hrow + DIM + tid, hb + hx / tot);
}

// ---------------------------------------------------------------------------
// Kernel 2: Y = leaky_relu(X[M,256] @ W[256,256]^T + b).  f32x2 packed GEMM.
// BM=64, BN=128, BK=32, 256 threads, microtile 4(M) x 8(N) as 4x4 f32x2 pairs.
// ---------------------------------------------------------------------------
__global__ __launch_bounds__(256, 2) void mlp_gemm(
    const float* __restrict__ X,
    const float* __restrict__ W,
    const float* __restrict__ bias,
    float*       __restrict__ Y)
{
    constexpr int BM = 64, BN = 128, BK = 32;
    constexpr int XP = 33;               // Xs pitch
    constexpr int WP = 132;              // Ws_t pitch (mult of 4 for LDS.128)
    __shared__ float Xs  [BM * XP];
    __shared__ __align__(16) float Ws_t[BK * WP];

    const int bn0 = blockIdx.x * BN;
    const int bm0 = blockIdx.y * BM;
    const int tid = threadIdx.x;
    const int tx  = tid & 15;
    const int ty  = tid >> 4;
    const int lr  = tid >> 3;            // 0..31
    const int lc  = (tid & 7) * 4;       // 0,4,...,28

    unsigned long long acc[4][4];
    #pragma unroll
    for (int m = 0; m < 4; m++)
        #pragma unroll
        for (int np = 0; np < 4; np++) acc[m][np] = 0ull;

    for (int k0 = 0; k0 < DIM2; k0 += BK) {
        #pragma unroll
        for (int r = 0; r < BM; r += 32) {
            const float4 x4 = *(const float4*)(X + (size_t)(bm0 + lr + r) * DIM2 + k0 + lc);
            float* d = Xs + (lr + r) * XP + lc;
            d[0] = x4.x; d[1] = x4.y; d[2] = x4.z; d[3] = x4.w;
        }
        #pragma unroll
        for (int r = 0; r < BN; r += 32) {
            const float4 w4 = *(const float4*)(W + (size_t)(bn0 + lr + r) * DIM2 + k0 + lc);
            Ws_t[(lc + 0) * WP + lr + r] = w4.x;
            Ws_t[(lc + 1) * WP + lr + r] = w4.y;
            Ws_t[(lc + 2) * WP + lr + r] = w4.z;
            Ws_t[(lc + 3) * WP + lr + r] = w4.w;
        }
        __syncthreads();

        #pragma unroll 8
        for (int k = 0; k < BK; k++) {
            unsigned long long a2[4];
            #pragma unroll
            for (int m = 0; m < 4; m++) {
                const float a = Xs[(ty * 4 + m) * XP + k];
                PACKDUP(a2[m], a);
            }
            const ulonglong2 wlo = *(const ulonglong2*)(Ws_t + k * WP + tx * 8);
            const ulonglong2 whi = *(const ulonglong2*)(Ws_t + k * WP + tx * 8 + 4);
            #pragma unroll
            for (int m = 0; m < 4; m++) {
                FMA2(acc[m][0], a2[m], wlo.x);
                FMA2(acc[m][1], a2[m], wlo.y);
                FMA2(acc[m][2], a2[m], whi.x);
                FMA2(acc[m][3], a2[m], whi.y);
            }
        }
        __syncthreads();
    }

    float bv[8];
    #pragma unroll
    for (int j = 0; j < 8; j++) bv[j] = bias[bn0 + tx * 8 + j];

    #pragma unroll
    for (int m = 0; m < 4; m++) {
        float o[8];
        #pragma unroll
        for (int np = 0; np < 4; np++) {
            o[np * 2 + 0] = __uint_as_float((unsigned)(acc[m][np] & 0xffffffffull));
            o[np * 2 + 1] = __uint_as_float((unsigned)(acc[m][np] >> 32));
        }
        float* yrow = Y + (size_t)(bm0 + ty * 4 + m) * DIM2 + bn0 + tx * 8;
        #pragma unroll
        for (int j4 = 0; j4 < 8; j4 += 4) {
            float4 vv;
            float t0 = o[j4 + 0] + bv[j4 + 0];
            float t1 = o[j4 + 1] + bv[j4 + 1];
            float t2 = o[j4 + 2] + bv[j4 + 2];
            float t3 = o[j4 + 3] + bv[j4 + 3];
            vv.x = t0 >= 0.f ? t0 : 0.01f * t0;
            vv.y = t1 >= 0.f ? t1 : 0.01f * t1;
            vv.z = t2 >= 0.f ? t2 : 0.01f * t2;
            vv.w = t3 >= 0.f ? t3 : 0.01f * t3;
            // evict-first: scratch must not displace the embedding tables in L2
            __stcs((float4*)(yrow + j4), vv);
        }
    }
}

// ---------------------------------------------------------------------------
// Kernel 3: out[m] = dot(X[m,:], out_w) + out_b.  One warp per row.
// ---------------------------------------------------------------------------
__global__ __launch_bounds__(256) void head_kernel(
    const float* __restrict__ X,
    const float* __restrict__ w3,
    const float* __restrict__ b3,
    float*       __restrict__ out)
{
    const int row  = blockIdx.x * 8 + (threadIdx.x >> 5);
    const int lane = threadIdx.x & 31;
    const float* xr = X + (size_t)row * DIM2;

    const float4 x1 = *(const float4*)(xr + lane * 4);
    const float4 x2 = *(const float4*)(xr + DIM + lane * 4);
    const float4 w1 = *(const float4*)(w3 + lane * 4);
    const float4 w2 = *(const float4*)(w3 + DIM + lane * 4);

    float s = x1.x * w1.x + x1.y * w1.y + x1.z * w1.z + x1.w * w1.w
            + x2.x * w2.x + x2.y * w2.y + x2.z * w2.z + x2.w * w2.w;
    #pragma unroll
    for (int o = 16; o > 0; o >>= 1)
        s += __shfl_xor_sync(0xffffffffu, s, o);
    if (lane == 0) out[row] = s + b3[0];
}

// ---------------------------------------------------------------------------
extern "C" void kernel_launch(void* const* d_in, const int* in_sizes, int n_in,
                              void* d_out, int out_size)
{
    const int*  x_u    = (const int*)   d_in[0];
    const int*  x_b    = (const int*)   d_in[1];
    const int*  items  = (const int*)   d_in[2];
    const int*  mask   = (const int*)   d_in[3];
    const float* emb_u = (const float*) d_in[4];
    const float* emb_i = (const float*) d_in[5];
    const float* emb_b = (const float*) d_in[6];
    const float* A     = (const float*) d_in[7];
    const float* fc1_w = (const float*) d_in[8];
    const float* fc1_b = (const float*) d_in[9];
    const float* fc2_w = (const float*) d_in[10];
    const float* fc2_b = (const float*) d_in[11];
    const float* out_w = (const float*) d_in[12];
    const float* out_b = (const float*) d_in[13];
    float* out = (float*)d_out;

    float *H, *T1, *T2;
    cudaGetSymbolAddress((void**)&H,  g_H);
    cudaGetSymbolAddress((void**)&T1, g_T1);
    cudaGetSymbolAddress((void**)&T2, g_T2);

    attn_kernel<<<BATCH, 128>>>(x_u, x_b, items, mask, emb_u, emb_i, emb_b, A);

    dim3 ggrid(DIM2 / 128, BATCH / 64);   // (2, 128)
    mlp_gemm<<<ggrid, 256>>>(H,  fc1_w, fc1_b, T1);
    mlp_gemm<<<ggrid, 256>>>(T1, fc2_w, fc2_b, T2);

    head_kernel<<<BATCH / 8, 256>>>(T2, out_w, out_b, out);
}